// round 11
// baseline (speedup 1.0000x reference)
#include <cuda_runtime.h>
#include <math.h>

#define HH 160
#define WW 160
#define BB 4
#define CIN 64
#define COUT 64
#define KKK 9
#define PADK 4
#define HWSZ (HH*WW)
#define NPIX (BB*HH*WW)      /* 102400 */
#define EPSV 1e-5f
#define NBLK_A 100           /* 25600 threads / 256 */
#define WT 80                /* w-tile per block */

// ---------------- device scratch ----------------
__device__ __align__(16) float g_off9[BB*KKK*HH*WW];
__device__ float g_partials[NBLK_A*18];
__device__ float g_scale[KKK];
__device__ float g_shift[KKK];
__device__ __align__(16) float g_wdefT[KKK*CIN*COUT];  // [k][c][o]

// ---------------- packed f32x2 helpers ----------------
__device__ __forceinline__ unsigned long long pack2(float v) {
    unsigned long long r;
    asm("mov.b64 %0, {%1, %1};" : "=l"(r) : "f"(v));
    return r;
}
__device__ __forceinline__ unsigned long long fma2(unsigned long long a,
                                                   unsigned long long b,
                                                   unsigned long long c) {
    unsigned long long d;
    asm("fma.rn.f32x2 %0, %1, %2, %3;" : "=l"(d) : "l"(a), "l"(b), "l"(c));
    return d;
}
__device__ __forceinline__ unsigned long long add2(unsigned long long a,
                                                   unsigned long long b) {
    unsigned long long d;
    asm("add.rn.f32x2 %0, %1, %2;" : "=l"(d) : "l"(a), "l"(b));
    return d;
}
__device__ __forceinline__ float2 unpack2(unsigned long long v) {
    float2 f;
    asm("mov.b64 {%0, %1}, %2;" : "=f"(f.x), "=f"(f.y) : "l"(v));
    return f;
}

// ---------------- kernel W: transpose w_def [o][c][k] -> [k][c][o] ----------------
__global__ void transpose_wdef_kernel(const float* __restrict__ w_def) {
    int idx = blockIdx.x*256 + threadIdx.x;
    if (idx >= COUT*CIN*KKK) return;
    int o = idx/(CIN*KKK);
    int c = (idx/KKK)%CIN;
    int k = idx%KKK;
    g_wdefT[(k*CIN + c)*COUT + o] = w_def[idx];
}

// ---------------- kernel A: offset conv (9 odd channels) + partial stats ----------------
__global__ __launch_bounds__(256) void offset_conv_kernel(
        const float* __restrict__ x,
        const float* __restrict__ w_off,
        const float* __restrict__ b_off) {
    __shared__ float wsm[576*12];
    __shared__ float bo[KKK];
    __shared__ float red[8*18];

    int tid = threadIdx.x;
    for (int e = tid; e < 576*9; e += 256) {
        int j = e % 9;
        int ck = e / 9;
        wsm[ck*12 + j] = w_off[(2*j+1)*576 + ck];
    }
    if (tid < 9) bo[tid] = b_off[2*tid+1];
    __syncthreads();

    int g  = blockIdx.x*256 + tid;
    int w4 = g % 40;
    int h  = (g/40) % HH;
    int b  = g / (40*HH);

    float4 acc[9];
#pragma unroll
    for (int j = 0; j < 9; j++) acc[j] = make_float4(bo[j], bo[j], bo[j], bo[j]);

    const float* xb = x + (size_t)b*CIN*HWSZ + w4*4;

#pragma unroll
    for (int ky = 0; ky < 9; ky++) {
        int row = h - PADK + ky;
        if ((unsigned)row >= (unsigned)HH) continue;
        const float* xr = xb + row*WW;
#pragma unroll 4
        for (int c = 0; c < CIN; c++) {
            float4 xv = *(const float4*)(xr + c*HWSZ);
            const float* wr = &wsm[(c*9 + ky)*12];
            float4 wA = *(const float4*)wr;
            float4 wB = *(const float4*)(wr + 4);
            float  w8 = wr[8];
#define FMA4(A, S) { A.x += xv.x*(S); A.y += xv.y*(S); A.z += xv.z*(S); A.w += xv.w*(S); }
            FMA4(acc[0], wA.x); FMA4(acc[1], wA.y); FMA4(acc[2], wA.z); FMA4(acc[3], wA.w);
            FMA4(acc[4], wB.x); FMA4(acc[5], wB.y); FMA4(acc[6], wB.z); FMA4(acc[7], wB.w);
            FMA4(acc[8], w8);
#undef FMA4
        }
    }

#pragma unroll
    for (int j = 0; j < 9; j++) {
        *(float4*)&g_off9[((size_t)(b*9 + j)*HH + h)*WW + w4*4] = acc[j];
    }

    float ls[9], ls2[9];
#pragma unroll
    for (int j = 0; j < 9; j++) {
        float4 a = acc[j];
        ls[j]  = a.x + a.y + a.z + a.w;
        ls2[j] = a.x*a.x + a.y*a.y + a.z*a.z + a.w*a.w;
    }
#pragma unroll
    for (int off = 16; off > 0; off >>= 1) {
#pragma unroll
        for (int j = 0; j < 9; j++) {
            ls[j]  += __shfl_down_sync(0xffffffffu, ls[j],  off);
            ls2[j] += __shfl_down_sync(0xffffffffu, ls2[j], off);
        }
    }
    int lane = tid & 31, wid = tid >> 5;
    if (lane == 0) {
#pragma unroll
        for (int j = 0; j < 9; j++) {
            red[wid*18 + j]     = ls[j];
            red[wid*18 + 9 + j] = ls2[j];
        }
    }
    __syncthreads();
    if (tid < 18) {
        float s = 0.f;
#pragma unroll
        for (int i = 0; i < 8; i++) s += red[i*18 + tid];
        g_partials[blockIdx.x*18 + tid] = s;
    }
}

// ---------------- kernel B: finalize stats ----------------
__global__ void stats_kernel(const float* __restrict__ gamma,
                             const float* __restrict__ beta) {
    __shared__ float sm[18];
    int tid = threadIdx.x;
    if (tid < 18) {
        float s = 0.f;
        for (int i = 0; i < NBLK_A; i++) s += g_partials[i*18 + tid];
        sm[tid] = s;
    }
    __syncthreads();
    if (tid < 9) {
        float mean = sm[tid] * (1.0f/(float)NPIX);
        float var  = sm[9+tid] * (1.0f/(float)NPIX) - mean*mean;
        float rstd = rsqrtf(fmaxf(var, 0.f) + EPSV);
        float sc   = rstd * gamma[2*tid+1];
        g_scale[tid] = sc;
        g_shift[tid] = beta[2*tid+1] - mean*sc;
    }
}

// ---------------- kernel C: deformable conv (warp-autonomous, no k-loop barriers) ----------------
// Block = (h, whalf, b). Tile 64 o x 80 w. 320 threads = 10 warps.
// Warp wid: cs = wid & 1 (channel half), wrange = wid >> 1 (16-w range).
// Warp tile: 64 o x 16 w x 32 c, double-buffered private smem samples (2 x 512 floats).
// Lane: og = lane & 7 (o = og*8..+7), wq = lane >> 3 (w = wbase16 + wq*4..+3).
// Gather lane: gwl = lane & 15 (w col), gch = lane >> 4 (c parity), 16 samples/lane/k.
// Weights: direct __ldg from g_wdefT[k][c][o] (L1-hot).
// Smem (floats):
//   wbuf  10 warps x 2 x 512        (40960 B)   also reused as epilogue partials
//   sw01  [9*80] float2             ( 5760 B)
//   a01   [9*80] short2             ( 2880 B)
#define SMEM_WBUF  0
#define SMEM_SW01  (10*1024)
#define SMEM_A01   (SMEM_SW01 + 2*9*WT)
#define SMEM_TOT_ELEMS (SMEM_A01 + 9*WT)
// = 10240 + 1440 + 720 = 12400 floats = 49600 B -> 3 blocks/SM (reg-capped)

extern __shared__ float dsm[];

__global__ __launch_bounds__(320, 3) void deform_kernel(
        const float* __restrict__ x,
        const float* __restrict__ b_def,
        float* __restrict__ out) {
    float2* sw01 = (float2*)(dsm + SMEM_SW01);
    short2* a01  = (short2*)(dsm + SMEM_A01);

    int tid = threadIdx.x;
    int h  = blockIdx.x;
    int w0 = blockIdx.y * WT;
    int b  = blockIdx.z;

    // ---- phase 0: offsets (tanh + cumulative convert + interp params) ----
    if (tid < WT) {
        int w = w0 + tid;
        float y[9], dx[9];
#pragma unroll
        for (int k = 0; k < 9; k++) {
            float v = g_off9[((size_t)(b*9 + k)*HH + h)*WW + w];
            y[k] = tanhf(v*g_scale[k] + g_shift[k]);
        }
        dx[4] = y[4];
        float a = y[4];
#pragma unroll
        for (int k = 3; k >= 0; k--) { a += y[k]; dx[k] = a; }
        a = y[4];
#pragma unroll
        for (int k = 5; k < 9; k++) { a += y[k]; dx[k] = a; }
#pragma unroll
        for (int k = 0; k < 9; k++) {
            float px = (float)w + dx[k];
            float fl = floorf(px);
            float fx = px - fl;
            int   x0 = (int)fl;
            float w0v = (x0 >= 0 && x0 < WW)      ? (1.f - fx) : 0.f;
            float w1v = (x0 >= -1 && x0 < WW - 1) ? fx         : 0.f;
            sw01[k*WT + tid] = make_float2(w0v, w1v);
            a01[k*WT + tid]  = make_short2((short)min(max(x0,     0), WW - 1),
                                           (short)min(max(x0 + 1, 0), WW - 1));
        }
    }

    const int lane = tid & 31;
    const int wid  = tid >> 5;
    const int cs      = wid & 1;        // channel half
    const int wrange  = wid >> 1;       // 0..4
    const int wbase16 = wrange * 16;
    const int cbase   = cs * 32;

    const int og = lane & 7;            // compute: output group
    const int wq = lane >> 3;           // compute: w quad (0..3)
    const int gwl = lane & 15;          // gather: w column in range
    const int gch = lane >> 4;          // gather: c parity (0/1)

    float* swarp = dsm + SMEM_WBUF + wid*1024;   // 2 x 512 floats

    unsigned long long acc[4][4];
#pragma unroll
    for (int p = 0; p < 4; p++)
#pragma unroll
        for (int j = 0; j < 4; j++) acc[p][j] = 0ull;

    const float* xbatch = x + (size_t)b*CIN*HWSZ;

    int r0 = max(h - PADK, 0);
    int r1 = min(h + PADK, HH - 1);
    int nk = r1 - r0 + 1;
    int k0 = r0 - h + PADK;

    __syncthreads();   // tables ready — last block-wide barrier until epilogue

    // ---- prologue: gather k0 into buffer 0 ----
    {
        const float* xrow = xbatch + (size_t)r0*WW;
        int oidx = k0*WT + wbase16 + gwl;
        float2 iw = sw01[oidx];
        short2 aa = a01[oidx];
        const float* p0 = xrow + aa.x;
        const float* p1 = xrow + aa.y;
#pragma unroll 16
        for (int j = 0; j < 16; j++) {
            int c = cbase + gch + 2*j;
            swarp[(gch + 2*j)*16 + gwl] = iw.x*__ldg(p0 + c*HWSZ) + iw.y*__ldg(p1 + c*HWSZ);
        }
    }
    __syncwarp();

    for (int i = 0; i < nk; i++) {
        int k = k0 + i;

        // gather k+1 into the other buffer (LDGs overlap compute below)
        if (i + 1 < nk) {
            const float* xrow = xbatch + (size_t)(r0 + i + 1)*WW;
            int oidx = (k + 1)*WT + wbase16 + gwl;
            float2 iw = sw01[oidx];
            short2 aa = a01[oidx];
            const float* p0 = xrow + aa.x;
            const float* p1 = xrow + aa.y;
            float* snext = swarp + ((i + 1) & 1)*512;
#pragma unroll 16
            for (int j = 0; j < 16; j++) {
                int c = cbase + gch + 2*j;
                snext[(gch + 2*j)*16 + gwl] = iw.x*__ldg(p0 + c*HWSZ) + iw.y*__ldg(p1 + c*HWSZ);
            }
        }

        // compute k from current buffer
        const float* sb  = swarp + (i & 1)*512;
        const float* wkg = g_wdefT + (size_t)k*CIN*COUT + og*8;
#pragma unroll 4
        for (int cc = 0; cc < 32; cc++) {
            float4 sv = *(const float4*)&sb[cc*16 + wq*4];
            unsigned long long s0 = pack2(sv.x);
            unsigned long long s1 = pack2(sv.y);
            unsigned long long s2 = pack2(sv.z);
            unsigned long long s3 = pack2(sv.w);
            const ulonglong2* wr = (const ulonglong2*)(wkg + (cbase + cc)*COUT);
            ulonglong2 wA = __ldg(wr);      // o-pairs (0,1),(2,3) of this og
            ulonglong2 wB = __ldg(wr + 1);  // o-pairs (4,5),(6,7)
            acc[0][0] = fma2(wA.x, s0, acc[0][0]);
            acc[0][1] = fma2(wA.x, s1, acc[0][1]);
            acc[0][2] = fma2(wA.x, s2, acc[0][2]);
            acc[0][3] = fma2(wA.x, s3, acc[0][3]);
            acc[1][0] = fma2(wA.y, s0, acc[1][0]);
            acc[1][1] = fma2(wA.y, s1, acc[1][1]);
            acc[1][2] = fma2(wA.y, s2, acc[1][2]);
            acc[1][3] = fma2(wA.y, s3, acc[1][3]);
            acc[2][0] = fma2(wB.x, s0, acc[2][0]);
            acc[2][1] = fma2(wB.x, s1, acc[2][1]);
            acc[2][2] = fma2(wB.x, s2, acc[2][2]);
            acc[2][3] = fma2(wB.x, s3, acc[2][3]);
            acc[3][0] = fma2(wB.y, s0, acc[3][0]);
            acc[3][1] = fma2(wB.y, s1, acc[3][1]);
            acc[3][2] = fma2(wB.y, s2, acc[3][2]);
            acc[3][3] = fma2(wB.y, s3, acc[3][3]);
        }
        __syncwarp();   // compute-k reads done before gather-(k+2) overwrites
    }

    // ---- epilogue: combine c-halves, add bias, store ----
    __syncthreads();   // all warps done; wbuf region dead
    unsigned long long* part = (unsigned long long*)(dsm + SMEM_WBUF);  // 2560 u64 = 20480 B
    int pidx = (wrange*32 + lane)*16;
    if (cs == 1) {
#pragma unroll
        for (int p = 0; p < 4; p++)
#pragma unroll
            for (int j = 0; j < 4; j++)
                part[pidx + p*4 + j] = acc[p][j];
    }
    __syncthreads();
    if (cs == 0) {
#pragma unroll
        for (int p = 0; p < 4; p++) {
            int o0 = og*8 + 2*p;
            float bv0 = __ldg(&b_def[o0]);
            float bv1 = __ldg(&b_def[o0+1]);
            float2 f[4];
#pragma unroll
            for (int j = 0; j < 4; j++) {
                unsigned long long v = add2(acc[p][j], part[pidx + p*4 + j]);
                f[j] = unpack2(v);
            }
            int wout = w0 + wbase16 + wq*4;
            float4 q0 = make_float4(f[0].x + bv0, f[1].x + bv0, f[2].x + bv0, f[3].x + bv0);
            float4 q1 = make_float4(f[0].y + bv1, f[1].y + bv1, f[2].y + bv1, f[3].y + bv1);
            *(float4*)&out[(((size_t)b*COUT + o0  )*HH + h)*WW + wout] = q0;
            *(float4*)&out[(((size_t)b*COUT + o0+1)*HH + h)*WW + wout] = q1;
        }
    }
}

// ---------------- launch ----------------
extern "C" void kernel_launch(void* const* d_in, const int* in_sizes, int n_in,
                              void* d_out, int out_size) {
    const float* x     = (const float*)d_in[0];
    const float* w_off = (const float*)d_in[1];
    const float* b_off = (const float*)d_in[2];
    const float* gamma = (const float*)d_in[3];
    const float* beta  = (const float*)d_in[4];
    const float* w_def = (const float*)d_in[5];
    const float* b_def = (const float*)d_in[6];
    float* out = (float*)d_out;

    static bool attr_set = false;
    if (!attr_set) {
        cudaFuncSetAttribute(deform_kernel,
                             cudaFuncAttributeMaxDynamicSharedMemorySize,
                             SMEM_TOT_ELEMS * (int)sizeof(float));
        attr_set = true;
    }

    transpose_wdef_kernel<<<(COUT*CIN*KKK + 255)/256, 256>>>(w_def);
    offset_conv_kernel<<<NBLK_A, 256>>>(x, w_off, b_off);
    stats_kernel<<<1, 32>>>(gamma, beta);
    deform_kernel<<<dim3(HH, WW/WT, BB), 320, SMEM_TOT_ELEMS * (int)sizeof(float)>>>(x, b_def, out);
}

// round 13
// speedup vs baseline: 1.7967x; 1.7967x over previous
#include <cuda_runtime.h>
#include <cuda_bf16.h>
#include <math.h>
#include <stdint.h>

#define HH 160
#define WW 160
#define BB 4
#define CIN 64
#define COUT 64
#define KKK 9
#define PADK 4
#define HWSZ (HH*WW)
#define NPIX (BB*HH*WW)      /* 102400 */
#define EPSV 1e-5f
#define NBLK_A 100
#define WT 80                /* w-tile per deform block */
#define WPAD 72              /* padded row length (bf16 elems): 144 B */

// ---------------- device scratch ----------------
__device__ __align__(16) float g_off9[BB*KKK*HH*WW];
__device__ float g_partials[NBLK_A*18];
__device__ float g_scale[KKK];
__device__ float g_shift[KKK];
// pre-split padded weights: [k][hi|lo][64 o][72 c] bf16 (18432 B per k)
__device__ __align__(16) __nv_bfloat16 g_wbf[KKK*2*64*WPAD];

// ---------------- kernel P: prep split weights ----------------
__global__ void wprep_kernel(const float* __restrict__ w_def) {
    int idx = blockIdx.x*256 + threadIdx.x;
    if (idx >= KKK*64*64) return;
    int k = idx / (64*64);
    int o = (idx / 64) % 64;
    int c = idx % 64;
    float v = w_def[o*576 + c*9 + k];           // w_def[o][c][k][0]
    __nv_bfloat16 hi = __float2bfloat16(v);
    __nv_bfloat16 lo = __float2bfloat16(v - __bfloat162float(hi));
    g_wbf[((size_t)(k*2+0)*64 + o)*WPAD + c] = hi;
    g_wbf[((size_t)(k*2+1)*64 + o)*WPAD + c] = lo;
}

// ---------------- kernel A: offset conv (9 odd channels) + partial stats ----------------
__global__ __launch_bounds__(256) void offset_conv_kernel(
        const float* __restrict__ x,
        const float* __restrict__ w_off,
        const float* __restrict__ b_off) {
    __shared__ float wsm[576*12];
    __shared__ float bo[KKK];
    __shared__ float red[8*18];

    int tid = threadIdx.x;
    for (int e = tid; e < 576*9; e += 256) {
        int j = e % 9;
        int ck = e / 9;
        wsm[ck*12 + j] = w_off[(2*j+1)*576 + ck];
    }
    if (tid < 9) bo[tid] = b_off[2*tid+1];
    __syncthreads();

    int g  = blockIdx.x*256 + tid;
    int w4 = g % 40;
    int h  = (g/40) % HH;
    int b  = g / (40*HH);

    float4 acc[9];
#pragma unroll
    for (int j = 0; j < 9; j++) acc[j] = make_float4(bo[j], bo[j], bo[j], bo[j]);

    const float* xb = x + (size_t)b*CIN*HWSZ + w4*4;

#pragma unroll
    for (int ky = 0; ky < 9; ky++) {
        int row = h - PADK + ky;
        if ((unsigned)row >= (unsigned)HH) continue;
        const float* xr = xb + row*WW;
#pragma unroll 4
        for (int c = 0; c < CIN; c++) {
            float4 xv = *(const float4*)(xr + c*HWSZ);
            const float* wr = &wsm[(c*9 + ky)*12];
            float4 wA = *(const float4*)wr;
            float4 wB = *(const float4*)(wr + 4);
            float  w8 = wr[8];
#define FMA4(A, S) { A.x += xv.x*(S); A.y += xv.y*(S); A.z += xv.z*(S); A.w += xv.w*(S); }
            FMA4(acc[0], wA.x); FMA4(acc[1], wA.y); FMA4(acc[2], wA.z); FMA4(acc[3], wA.w);
            FMA4(acc[4], wB.x); FMA4(acc[5], wB.y); FMA4(acc[6], wB.z); FMA4(acc[7], wB.w);
            FMA4(acc[8], w8);
#undef FMA4
        }
    }

#pragma unroll
    for (int j = 0; j < 9; j++) {
        *(float4*)&g_off9[((size_t)(b*9 + j)*HH + h)*WW + w4*4] = acc[j];
    }

    float ls[9], ls2[9];
#pragma unroll
    for (int j = 0; j < 9; j++) {
        float4 a = acc[j];
        ls[j]  = a.x + a.y + a.z + a.w;
        ls2[j] = a.x*a.x + a.y*a.y + a.z*a.z + a.w*a.w;
    }
#pragma unroll
    for (int off = 16; off > 0; off >>= 1) {
#pragma unroll
        for (int j = 0; j < 9; j++) {
            ls[j]  += __shfl_down_sync(0xffffffffu, ls[j],  off);
            ls2[j] += __shfl_down_sync(0xffffffffu, ls2[j], off);
        }
    }
    int lane = tid & 31, wid = tid >> 5;
    if (lane == 0) {
#pragma unroll
        for (int j = 0; j < 9; j++) {
            red[wid*18 + j]     = ls[j];
            red[wid*18 + 9 + j] = ls2[j];
        }
    }
    __syncthreads();
    if (tid < 18) {
        float s = 0.f;
#pragma unroll
        for (int i = 0; i < 8; i++) s += red[i*18 + tid];
        g_partials[blockIdx.x*18 + tid] = s;
    }
}

// ---------------- kernel B: finalize stats ----------------
__global__ void stats_kernel(const float* __restrict__ gamma,
                             const float* __restrict__ beta) {
    __shared__ float sm[18];
    int tid = threadIdx.x;
    if (tid < 18) {
        float s = 0.f;
        for (int i = 0; i < NBLK_A; i++) s += g_partials[i*18 + tid];
        sm[tid] = s;
    }
    __syncthreads();
    if (tid < 9) {
        float mean = sm[tid] * (1.0f/(float)NPIX);
        float var  = sm[9+tid] * (1.0f/(float)NPIX) - mean*mean;
        float rstd = rsqrtf(fmaxf(var, 0.f) + EPSV);
        float sc   = rstd * gamma[2*tid+1];
        g_scale[tid] = sc;
        g_shift[tid] = beta[2*tid+1] - mean*sc;
    }
}

// ---------------- kernel C: deformable conv via mma.sync bf16 3-split ----------------
// Block = (h, whalf, b), 256 threads (8 warps). D[64o][80w] in fp32 regs.
// Warp: mi = wid%4 (o rows mi*16..+15), ni = wid/4 (w cols ni*40..+39, 5 n8-tiles).
// Per k: stage W hi/lo [64][72]bf16 (straight copy) + gather/split S hi/lo [80][72]bf16;
// then 4 k16-chunks x 5 n8-tiles x 3 split-terms of mma.sync.m16n8k16.
// Fragment loads are plain LDS.32 (row-major A [o][c]; S[w][c] = col-major B);
// 144 B row pitch -> conflict-free (bank = 4*row + t).
// Smem bytes:
//   [0]      W_hi 9216 | [9216]  W_lo 9216
//   [18432]  S_hi 11520 | [29952] S_lo 11520
//   [41472]  sw01 float2[720] 5760 | [47232] a01 short2[720] 2880  -> 50112 total
#define SM_WHI 0
#define SM_WLO 9216
#define SM_SHI 18432
#define SM_SLO 29952
#define SM_TBL 41472
#define SMEM_BYTES 50112

extern __shared__ unsigned char smraw[];

__device__ __forceinline__ void mma_bf16(float* d, const uint32_t* a, const uint32_t* bfr) {
    asm volatile(
        "mma.sync.aligned.m16n8k16.row.col.f32.bf16.bf16.f32 "
        "{%0,%1,%2,%3}, {%4,%5,%6,%7}, {%8,%9}, {%0,%1,%2,%3};"
        : "+f"(d[0]), "+f"(d[1]), "+f"(d[2]), "+f"(d[3])
        : "r"(a[0]), "r"(a[1]), "r"(a[2]), "r"(a[3]), "r"(bfr[0]), "r"(bfr[1]));
}

__global__ __launch_bounds__(256, 4) void deform_mma_kernel(
        const float* __restrict__ x,
        const float* __restrict__ b_def,
        float* __restrict__ out) {
    float2* sw01 = (float2*)(smraw + SM_TBL);
    short2* a01  = (short2*)(smraw + SM_TBL + 5760);

    int tid = threadIdx.x;
    int lane = tid & 31;
    int wid  = tid >> 5;
    int h  = blockIdx.x;
    int w0 = blockIdx.y * WT;
    int b  = blockIdx.z;

    // ---- phase 0: offsets (tanh + cumulative convert + interp params) ----
    if (tid < WT) {
        int w = w0 + tid;
        float y[9], dx[9];
#pragma unroll
        for (int k = 0; k < 9; k++) {
            float v = g_off9[((size_t)(b*9 + k)*HH + h)*WW + w];
            y[k] = tanhf(v*g_scale[k] + g_shift[k]);
        }
        dx[4] = y[4];
        float a = y[4];
#pragma unroll
        for (int k = 3; k >= 0; k--) { a += y[k]; dx[k] = a; }
        a = y[4];
#pragma unroll
        for (int k = 5; k < 9; k++) { a += y[k]; dx[k] = a; }
#pragma unroll
        for (int k = 0; k < 9; k++) {
            float px = (float)w + dx[k];
            float fl = floorf(px);
            float fx = px - fl;
            int   x0 = (int)fl;
            float w0v = (x0 >= 0 && x0 < WW)      ? (1.f - fx) : 0.f;
            float w1v = (x0 >= -1 && x0 < WW - 1) ? fx         : 0.f;
            sw01[k*WT + tid] = make_float2(w0v, w1v);
            a01[k*WT + tid]  = make_short2((short)min(max(x0,     0), WW - 1),
                                           (short)min(max(x0 + 1, 0), WW - 1));
        }
    }

    const int mi = wid & 3;          // o tile: rows mi*16..+15
    const int ni = wid >> 2;         // w half: cols ni*40..+39
    const int grp = lane >> 2;       // 0..7
    const int tig = lane & 3;        // 0..3

    float acc[5][4];
#pragma unroll
    for (int nt = 0; nt < 5; nt++)
#pragma unroll
        for (int j = 0; j < 4; j++) acc[nt][j] = 0.f;

    const float* xbatch = x + (size_t)b*CIN*HWSZ;

    int r0 = max(h - PADK, 0);
    int r1 = min(h + PADK, HH - 1);
    int nk = r1 - r0 + 1;
    int k0 = r0 - h + PADK;

    for (int i = 0; i < nk; i++) {
        int k = k0 + i;
        __syncthreads();   // phase-0 done / smem free for reuse

        // stage split W tiles (18432 B straight copy)
        {
            const float4* wsrc = (const float4*)(g_wbf + (size_t)k*2*64*WPAD);
            float4* wdst = (float4*)(smraw + SM_WHI);
            for (int t = tid; t < 1152; t += 256) wdst[t] = wsrc[t];
        }
        // gather + interpolate + bf16-split S[w][c] (hi/lo)
        {
            const float* xrow = xbatch + (size_t)(r0 + i)*WW;
            for (int e = tid; e < WT*32; e += 256) {
                int w  = e % WT;
                int cp = e / WT;        // c pair 0..31
                int c  = cp*2;
                float2 iw = sw01[k*WT + w];
                short2 aa = a01[k*WT + w];
                const float* p0 = xrow + aa.x;
                const float* p1 = xrow + aa.y;
                float v0 = iw.x*__ldg(p0 + c*HWSZ)     + iw.y*__ldg(p1 + c*HWSZ);
                float v1 = iw.x*__ldg(p0 + (c+1)*HWSZ) + iw.y*__ldg(p1 + (c+1)*HWSZ);
                __nv_bfloat16 h0 = __float2bfloat16(v0);
                __nv_bfloat16 h1 = __float2bfloat16(v1);
                float l0 = v0 - __bfloat162float(h0);
                float l1 = v1 - __bfloat162float(h1);
                uint32_t hpair = ((uint32_t)__bfloat16_as_ushort(h1) << 16)
                               |  (uint32_t)__bfloat16_as_ushort(h0);
                uint32_t lpair;
                asm("cvt.rn.bf16x2.f32 %0, %1, %2;" : "=r"(lpair) : "f"(l1), "f"(l0));
                uint32_t off = (uint32_t)w*144 + (uint32_t)cp*4;
                *(uint32_t*)(smraw + SM_SHI + off) = hpair;
                *(uint32_t*)(smraw + SM_SLO + off) = lpair;
            }
        }
        __syncthreads();

        // GEMM: 4 k16 chunks
        const unsigned char* Whi = smraw + SM_WHI + (mi*16 + grp)*144;
        const unsigned char* Wlo = smraw + SM_WLO + (mi*16 + grp)*144;
        const unsigned char* Sbase = smraw + (size_t)0;
#pragma unroll
        for (int kc = 0; kc < 4; kc++) {
            uint32_t coff = kc*32 + tig*4;   // byte offset of col 2t within chunk
            uint32_t ah[4], al[4];
            ah[0] = *(const uint32_t*)(Whi + coff);            // [g][2t]
            ah[1] = *(const uint32_t*)(Whi + 8*144 + coff);    // [g+8][2t]
            ah[2] = *(const uint32_t*)(Whi + coff + 16);       // [g][2t+8]
            ah[3] = *(const uint32_t*)(Whi + 8*144 + coff + 16);
            al[0] = *(const uint32_t*)(Wlo + coff);
            al[1] = *(const uint32_t*)(Wlo + 8*144 + coff);
            al[2] = *(const uint32_t*)(Wlo + coff + 16);
            al[3] = *(const uint32_t*)(Wlo + 8*144 + coff + 16);
#pragma unroll
            for (int nt = 0; nt < 5; nt++) {
                uint32_t srow = (ni*40 + nt*8 + grp)*144 + coff;
                uint32_t bh[2], bl[2];
                bh[0] = *(const uint32_t*)(smraw + SM_SHI + srow);       // k=2t,2t+1
                bh[1] = *(const uint32_t*)(smraw + SM_SHI + srow + 16);  // k=2t+8,+9
                bl[0] = *(const uint32_t*)(smraw + SM_SLO + srow);
                bl[1] = *(const uint32_t*)(smraw + SM_SLO + srow + 16);
                mma_bf16(acc[nt], ah, bh);
                mma_bf16(acc[nt], ah, bl);
                mma_bf16(acc[nt], al, bh);
            }
        }
        (void)Sbase;
    }

    // ---- epilogue: add bias, store float2 pairs ----
    int o0 = mi*16 + grp;
    int o1 = o0 + 8;
    float bv0 = __ldg(&b_def[o0]);
    float bv1 = __ldg(&b_def[o1]);
#pragma unroll
    for (int nt = 0; nt < 5; nt++) {
        int wcol = w0 + ni*40 + nt*8 + tig*2;
        float2 q0 = make_float2(acc[nt][0] + bv0, acc[nt][1] + bv0);
        float2 q1 = make_float2(acc[nt][2] + bv1, acc[nt][3] + bv1);
        *(float2*)&out[(((size_t)b*COUT + o0)*HH + h)*WW + wcol] = q0;
        *(float2*)&out[(((size_t)b*COUT + o1)*HH + h)*WW + wcol] = q1;
    }
}

// ---------------- launch ----------------
extern "C" void kernel_launch(void* const* d_in, const int* in_sizes, int n_in,
                              void* d_out, int out_size) {
    const float* x     = (const float*)d_in[0];
    const float* w_off = (const float*)d_in[1];
    const float* b_off = (const float*)d_in[2];
    const float* gamma = (const float*)d_in[3];
    const float* beta  = (const float*)d_in[4];
    const float* w_def = (const float*)d_in[5];
    const float* b_def = (const float*)d_in[6];
    float* out = (float*)d_out;

    static bool attr_set = false;
    if (!attr_set) {
        cudaFuncSetAttribute(deform_mma_kernel,
                             cudaFuncAttributeMaxDynamicSharedMemorySize, SMEM_BYTES);
        attr_set = true;
    }

    wprep_kernel<<<(KKK*64*64 + 255)/256, 256>>>(w_def);
    offset_conv_kernel<<<NBLK_A, 256>>>(x, w_off, b_off);
    stats_kernel<<<1, 32>>>(gamma, beta);
    deform_mma_kernel<<<dim3(HH, WW/WT, BB), 256, SMEM_BYTES>>>(x, b_def, out);
}

// round 14
// speedup vs baseline: 1.8844x; 1.0488x over previous
#include <cuda_runtime.h>
#include <cuda_bf16.h>
#include <math.h>
#include <stdint.h>

#define HH 160
#define WW 160
#define BB 4
#define CIN 64
#define COUT 64
#define KKK 9
#define PADK 4
#define HWSZ (HH*WW)
#define NPIX (BB*HH*WW)      /* 102400 */
#define EPSV 1e-5f
#define NBLK_A 100
#define WT 80                /* w-tile per deform block */
#define WPAD 72              /* padded row length (bf16 elems): 144 B */

// ---------------- device scratch ----------------
__device__ __align__(16) float g_off9[BB*KKK*HH*WW];
__device__ float g_partials[NBLK_A*18];
__device__ float g_scale[KKK];
__device__ float g_shift[KKK];
// pre-split padded weights: [k][hi|lo][64 o][72 c] bf16 (18432 B per k)
__device__ __align__(16) __nv_bfloat16 g_wbf[KKK*2*64*WPAD];

// ---------------- kernel P: prep split weights ----------------
__global__ void wprep_kernel(const float* __restrict__ w_def) {
    int idx = blockIdx.x*256 + threadIdx.x;
    if (idx >= KKK*64*64) return;
    int k = idx / (64*64);
    int o = (idx / 64) % 64;
    int c = idx % 64;
    float v = w_def[o*576 + c*9 + k];           // w_def[o][c][k][0]
    __nv_bfloat16 hi = __float2bfloat16(v);
    __nv_bfloat16 lo = __float2bfloat16(v - __bfloat162float(hi));
    g_wbf[((size_t)(k*2+0)*64 + o)*WPAD + c] = hi;
    g_wbf[((size_t)(k*2+1)*64 + o)*WPAD + c] = lo;
}

// ---------------- kernel A: offset conv (9 odd channels) + partial stats ----------------
__global__ __launch_bounds__(256) void offset_conv_kernel(
        const float* __restrict__ x,
        const float* __restrict__ w_off,
        const float* __restrict__ b_off) {
    __shared__ float wsm[576*12];
    __shared__ float bo[KKK];
    __shared__ float red[8*18];

    int tid = threadIdx.x;
    for (int e = tid; e < 576*9; e += 256) {
        int j = e % 9;
        int ck = e / 9;
        wsm[ck*12 + j] = w_off[(2*j+1)*576 + ck];
    }
    if (tid < 9) bo[tid] = b_off[2*tid+1];
    __syncthreads();

    int g  = blockIdx.x*256 + tid;
    int w4 = g % 40;
    int h  = (g/40) % HH;
    int b  = g / (40*HH);

    float4 acc[9];
#pragma unroll
    for (int j = 0; j < 9; j++) acc[j] = make_float4(bo[j], bo[j], bo[j], bo[j]);

    const float* xb = x + (size_t)b*CIN*HWSZ + w4*4;

#pragma unroll
    for (int ky = 0; ky < 9; ky++) {
        int row = h - PADK + ky;
        if ((unsigned)row >= (unsigned)HH) continue;
        const float* xr = xb + row*WW;
#pragma unroll 4
        for (int c = 0; c < CIN; c++) {
            float4 xv = *(const float4*)(xr + c*HWSZ);
            const float* wr = &wsm[(c*9 + ky)*12];
            float4 wA = *(const float4*)wr;
            float4 wB = *(const float4*)(wr + 4);
            float  w8 = wr[8];
#define FMA4(A, S) { A.x += xv.x*(S); A.y += xv.y*(S); A.z += xv.z*(S); A.w += xv.w*(S); }
            FMA4(acc[0], wA.x); FMA4(acc[1], wA.y); FMA4(acc[2], wA.z); FMA4(acc[3], wA.w);
            FMA4(acc[4], wB.x); FMA4(acc[5], wB.y); FMA4(acc[6], wB.z); FMA4(acc[7], wB.w);
            FMA4(acc[8], w8);
#undef FMA4
        }
    }

#pragma unroll
    for (int j = 0; j < 9; j++) {
        *(float4*)&g_off9[((size_t)(b*9 + j)*HH + h)*WW + w4*4] = acc[j];
    }

    float ls[9], ls2[9];
#pragma unroll
    for (int j = 0; j < 9; j++) {
        float4 a = acc[j];
        ls[j]  = a.x + a.y + a.z + a.w;
        ls2[j] = a.x*a.x + a.y*a.y + a.z*a.z + a.w*a.w;
    }
#pragma unroll
    for (int off = 16; off > 0; off >>= 1) {
#pragma unroll
        for (int j = 0; j < 9; j++) {
            ls[j]  += __shfl_down_sync(0xffffffffu, ls[j],  off);
            ls2[j] += __shfl_down_sync(0xffffffffu, ls2[j], off);
        }
    }
    int lane = tid & 31, wid = tid >> 5;
    if (lane == 0) {
#pragma unroll
        for (int j = 0; j < 9; j++) {
            red[wid*18 + j]     = ls[j];
            red[wid*18 + 9 + j] = ls2[j];
        }
    }
    __syncthreads();
    if (tid < 18) {
        float s = 0.f;
#pragma unroll
        for (int i = 0; i < 8; i++) s += red[i*18 + tid];
        g_partials[blockIdx.x*18 + tid] = s;
    }
}

// ---------------- kernel B: finalize stats ----------------
__global__ void stats_kernel(const float* __restrict__ gamma,
                             const float* __restrict__ beta) {
    __shared__ float sm[18];
    int tid = threadIdx.x;
    if (tid < 18) {
        float s = 0.f;
        for (int i = 0; i < NBLK_A; i++) s += g_partials[i*18 + tid];
        sm[tid] = s;
    }
    __syncthreads();
    if (tid < 9) {
        float mean = sm[tid] * (1.0f/(float)NPIX);
        float var  = sm[9+tid] * (1.0f/(float)NPIX) - mean*mean;
        float rstd = rsqrtf(fmaxf(var, 0.f) + EPSV);
        float sc   = rstd * gamma[2*tid+1];
        g_scale[tid] = sc;
        g_shift[tid] = beta[2*tid+1] - mean*sc;
    }
}

// ---------------- kernel C: deformable conv via mma.sync bf16 3-split + k-split ----------------
// Block = (h, whalf, b), 256 threads (8 warps): kh=wid&1 (k16-chunks kh*2..+1),
// ni=(wid>>1)&1 (w cols ni*40..+39), mi=wid>>2 (o rows mi*32..+31, 2 m16 tiles).
// Fragments via ldmatrix; epilogue reduces the two kh halves through smem.
// Smem bytes (same as R13):
//   [0] W_hi 9216 | [9216] W_lo 9216 | [18432] S_hi 11520 | [29952] S_lo 11520
//   [41472] sw01 float2[720] 5760 | [47232] a01 short2[720] 2880  -> 50112
//   epilogue overlay at [0]: partials float[5120] (20480 B)
#define SM_WHI 0
#define SM_WLO 9216
#define SM_SHI 18432
#define SM_SLO 29952
#define SM_TBL 41472
#define SMEM_BYTES 50112

extern __shared__ unsigned char smraw[];

__device__ __forceinline__ void mma_bf16(float* d, const uint32_t* a, const uint32_t* bfr) {
    asm volatile(
        "mma.sync.aligned.m16n8k16.row.col.f32.bf16.bf16.f32 "
        "{%0,%1,%2,%3}, {%4,%5,%6,%7}, {%8,%9}, {%0,%1,%2,%3};"
        : "+f"(d[0]), "+f"(d[1]), "+f"(d[2]), "+f"(d[3])
        : "r"(a[0]), "r"(a[1]), "r"(a[2]), "r"(a[3]), "r"(bfr[0]), "r"(bfr[1]));
}
__device__ __forceinline__ void ldsm_x4(uint32_t addr, uint32_t* r) {
    asm volatile("ldmatrix.sync.aligned.m8n8.x4.shared.b16 {%0,%1,%2,%3}, [%4];"
        : "=r"(r[0]), "=r"(r[1]), "=r"(r[2]), "=r"(r[3]) : "r"(addr));
}
__device__ __forceinline__ void ldsm_x2(uint32_t addr, uint32_t* r) {
    asm volatile("ldmatrix.sync.aligned.m8n8.x2.shared.b16 {%0,%1}, [%2];"
        : "=r"(r[0]), "=r"(r[1]) : "r"(addr));
}

__global__ __launch_bounds__(256, 3) void deform_mma_kernel(
        const float* __restrict__ x,
        const float* __restrict__ b_def,
        float* __restrict__ out) {
    float2* sw01 = (float2*)(smraw + SM_TBL);
    short2* a01  = (short2*)(smraw + SM_TBL + 5760);

    int tid = threadIdx.x;
    int lane = tid & 31;
    int wid  = tid >> 5;
    int h  = blockIdx.x;
    int w0 = blockIdx.y * WT;
    int b  = blockIdx.z;

    // ---- phase 0: offsets ----
    if (tid < WT) {
        int w = w0 + tid;
        float y[9], dx[9];
#pragma unroll
        for (int k = 0; k < 9; k++) {
            float v = g_off9[((size_t)(b*9 + k)*HH + h)*WW + w];
            y[k] = tanhf(v*g_scale[k] + g_shift[k]);
        }
        dx[4] = y[4];
        float a = y[4];
#pragma unroll
        for (int k = 3; k >= 0; k--) { a += y[k]; dx[k] = a; }
        a = y[4];
#pragma unroll
        for (int k = 5; k < 9; k++) { a += y[k]; dx[k] = a; }
#pragma unroll
        for (int k = 0; k < 9; k++) {
            float px = (float)w + dx[k];
            float fl = floorf(px);
            float fx = px - fl;
            int   x0 = (int)fl;
            float w0v = (x0 >= 0 && x0 < WW)      ? (1.f - fx) : 0.f;
            float w1v = (x0 >= -1 && x0 < WW - 1) ? fx         : 0.f;
            sw01[k*WT + tid] = make_float2(w0v, w1v);
            a01[k*WT + tid]  = make_short2((short)min(max(x0,     0), WW - 1),
                                           (short)min(max(x0 + 1, 0), WW - 1));
        }
    }

    const int kh = wid & 1;          // k-chunk half: kc = kh*2 + {0,1}
    const int ni = (wid >> 1) & 1;   // w half: cols ni*40..+39
    const int mi = wid >> 2;         // o tile: rows mi*32..+31
    const int grp = lane >> 2;       // 0..7
    const int tig = lane & 3;        // 0..3
    const int mat = lane >> 3;       // ldmatrix sub-matrix id
    const int rowin = lane & 7;

    uint32_t sbase = (uint32_t)__cvta_generic_to_shared(smraw);
    // ldmatrix per-lane offsets (bytes, excluding region base / kc)
    const uint32_t aoff  = (uint32_t)((mat & 1)*8*144 + rowin*144 + (mat >> 1)*16);
    const uint32_t boff4 = (uint32_t)((mat >> 1)*8*144 + rowin*144 + (mat & 1)*16);
    const uint32_t boff2 = (uint32_t)(rowin*144 + (mat & 1)*16);

    float acc[2][5][4];
#pragma unroll
    for (int mt = 0; mt < 2; mt++)
#pragma unroll
        for (int nt = 0; nt < 5; nt++)
#pragma unroll
            for (int j = 0; j < 4; j++) acc[mt][nt][j] = 0.f;

    const float* xbatch = x + (size_t)b*CIN*HWSZ;

    int r0 = max(h - PADK, 0);
    int r1 = min(h + PADK, HH - 1);
    int nk = r1 - r0 + 1;
    int k0 = r0 - h + PADK;

    for (int i = 0; i < nk; i++) {
        int k = k0 + i;
        __syncthreads();   // phase-0 done / smem free for reuse

        // stage split W tiles (18432 B straight copy)
        {
            const float4* wsrc = (const float4*)(g_wbf + (size_t)k*2*64*WPAD);
            float4* wdst = (float4*)(smraw + SM_WHI);
            for (int t = tid; t < 1152; t += 256) wdst[t] = wsrc[t];
        }
        // gather + interpolate + bf16-split S[w][c] (hi/lo)
        {
            const float* xrow = xbatch + (size_t)(r0 + i)*WW;
            for (int e = tid; e < WT*32; e += 256) {
                int w  = e % WT;
                int cp = e / WT;        // c pair 0..31
                int c  = cp*2;
                float2 iw = sw01[k*WT + w];
                short2 aa = a01[k*WT + w];
                const float* p0 = xrow + aa.x;
                const float* p1 = xrow + aa.y;
                float v0 = iw.x*__ldg(p0 + c*HWSZ)     + iw.y*__ldg(p1 + c*HWSZ);
                float v1 = iw.x*__ldg(p0 + (c+1)*HWSZ) + iw.y*__ldg(p1 + (c+1)*HWSZ);
                __nv_bfloat16 h0 = __float2bfloat16(v0);
                __nv_bfloat16 h1 = __float2bfloat16(v1);
                float l0 = v0 - __bfloat162float(h0);
                float l1 = v1 - __bfloat162float(h1);
                uint32_t hpair = ((uint32_t)__bfloat16_as_ushort(h1) << 16)
                               |  (uint32_t)__bfloat16_as_ushort(h0);
                uint32_t lpair;
                asm("cvt.rn.bf16x2.f32 %0, %1, %2;" : "=r"(lpair) : "f"(l1), "f"(l0));
                uint32_t off = (uint32_t)w*144 + (uint32_t)cp*4;
                *(uint32_t*)(smraw + SM_SHI + off) = hpair;
                *(uint32_t*)(smraw + SM_SLO + off) = lpair;
            }
        }
        __syncthreads();

        // GEMM: this warp's 2 k16 chunks
#pragma unroll
        for (int kcl = 0; kcl < 2; kcl++) {
            uint32_t kb = (uint32_t)(kh*2 + kcl)*32;
            uint32_t ah0[4], ah1[4], al0[4], al1[4];
            ldsm_x4(sbase + SM_WHI + (mi*32     )*144 + aoff + kb, ah0);
            ldsm_x4(sbase + SM_WHI + (mi*32 + 16)*144 + aoff + kb, ah1);
            ldsm_x4(sbase + SM_WLO + (mi*32     )*144 + aoff + kb, al0);
            ldsm_x4(sbase + SM_WLO + (mi*32 + 16)*144 + aoff + kb, al1);
#pragma unroll
            for (int ntp = 0; ntp < 2; ntp++) {    // tile pairs (0,1),(2,3)
                uint32_t bh[4], bl[4];
                uint32_t bb = (uint32_t)(ni*40 + ntp*16)*144 + boff4 + kb;
                ldsm_x4(sbase + SM_SHI + bb, bh);
                ldsm_x4(sbase + SM_SLO + bb, bl);
                int nt = 2*ntp;
                mma_bf16(acc[0][nt],   ah0, bh);     mma_bf16(acc[0][nt],   ah0, bl);
                mma_bf16(acc[0][nt],   al0, bh);
                mma_bf16(acc[1][nt],   ah1, bh);     mma_bf16(acc[1][nt],   ah1, bl);
                mma_bf16(acc[1][nt],   al1, bh);
                mma_bf16(acc[0][nt+1], ah0, bh+2);   mma_bf16(acc[0][nt+1], ah0, bl+2);
                mma_bf16(acc[0][nt+1], al0, bh+2);
                mma_bf16(acc[1][nt+1], ah1, bh+2);   mma_bf16(acc[1][nt+1], ah1, bl+2);
                mma_bf16(acc[1][nt+1], al1, bh+2);
            }
            {   // tile nt=4
                uint32_t bh[2], bl[2];
                uint32_t bb = (uint32_t)(ni*40 + 32)*144 + boff2 + kb;
                ldsm_x2(sbase + SM_SHI + bb, bh);
                ldsm_x2(sbase + SM_SLO + bb, bl);
                mma_bf16(acc[0][4], ah0, bh);  mma_bf16(acc[0][4], ah0, bl);
                mma_bf16(acc[0][4], al0, bh);
                mma_bf16(acc[1][4], ah1, bh);  mma_bf16(acc[1][4], ah1, bl);
                mma_bf16(acc[1][4], al1, bh);
            }
        }
    }

    // ---- epilogue: reduce kh halves via smem, add bias, store ----
    __syncthreads();                       // W/S regions dead
    float* part = (float*)smraw;           // 4 quads x 1280 floats = 20480 B
    int quad = mi*2 + ni;
    if (kh == 1) {
#pragma unroll
        for (int mt = 0; mt < 2; mt++)
#pragma unroll
            for (int nt = 0; nt < 5; nt++)
#pragma unroll
                for (int j = 0; j < 4; j++)
                    part[quad*1280 + ((mt*5 + nt)*4 + j)*32 + lane] = acc[mt][nt][j];
    }
    __syncthreads();
    if (kh == 0) {
#pragma unroll
        for (int mt = 0; mt < 2; mt++) {
            int o0 = mi*32 + mt*16 + grp;
            int o1 = o0 + 8;
            float bv0 = __ldg(&b_def[o0]);
            float bv1 = __ldg(&b_def[o1]);
#pragma unroll
            for (int nt = 0; nt < 5; nt++) {
                float r[4];
#pragma unroll
                for (int j = 0; j < 4; j++)
                    r[j] = acc[mt][nt][j] + part[quad*1280 + ((mt*5 + nt)*4 + j)*32 + lane];
                int wcol = w0 + ni*40 + nt*8 + tig*2;
                float2 q0 = make_float2(r[0] + bv0, r[1] + bv0);
                float2 q1 = make_float2(r[2] + bv1, r[3] + bv1);
                *(float2*)&out[(((size_t)b*COUT + o0)*HH + h)*WW + wcol] = q0;
                *(float2*)&out[(((size_t)b*COUT + o1)*HH + h)*WW + wcol] = q1;
            }
        }
    }
}

// ---------------- launch ----------------
extern "C" void kernel_launch(void* const* d_in, const int* in_sizes, int n_in,
                              void* d_out, int out_size) {
    const float* x     = (const float*)d_in[0];
    const float* w_off = (const float*)d_in[1];
    const float* b_off = (const float*)d_in[2];
    const float* gamma = (const float*)d_in[3];
    const float* beta  = (const float*)d_in[4];
    const float* w_def = (const float*)d_in[5];
    const float* b_def = (const float*)d_in[6];
    float* out = (float*)d_out;

    static bool attr_set = false;
    if (!attr_set) {
        cudaFuncSetAttribute(deform_mma_kernel,
                             cudaFuncAttributeMaxDynamicSharedMemorySize, SMEM_BYTES);
        attr_set = true;
    }

    wprep_kernel<<<(KKK*64*64 + 255)/256, 256>>>(w_def);
    offset_conv_kernel<<<NBLK_A, 256>>>(x, w_off, b_off);
    stats_kernel<<<1, 32>>>(gamma, beta);
    deform_mma_kernel<<<dim3(HH, WW/WT, BB), 256, SMEM_BYTES>>>(x, b_def, out);
}

// round 15
// speedup vs baseline: 2.0069x; 1.0650x over previous
#include <cuda_runtime.h>
#include <cuda_bf16.h>
#include <math.h>
#include <stdint.h>

#define HH 160
#define WW 160
#define BB 4
#define CIN 64
#define COUT 64
#define KKK 9
#define PADK 4
#define HWSZ (HH*WW)
#define NPIX (BB*HH*WW)      /* 102400 */
#define EPSV 1e-5f
#define NBLK_A 100
#define WT 80                /* w-tile per deform block */
#define WPAD 72              /* padded row length (bf16 elems): 144 B */

// ---------------- device scratch ----------------
__device__ __align__(16) float g_off9[BB*KKK*HH*WW];
__device__ float g_partials[NBLK_A*18];
__device__ float g_scale[KKK];
__device__ float g_shift[KKK];
// pre-split padded weights: [k][hi|lo][64 o][72 c] bf16 (18432 B per k)
__device__ __align__(16) __nv_bfloat16 g_wbf[KKK*2*64*WPAD];

// ---------------- kernel P: prep split weights ----------------
__global__ void wprep_kernel(const float* __restrict__ w_def) {
    int idx = blockIdx.x*256 + threadIdx.x;
    if (idx >= KKK*64*64) return;
    int k = idx / (64*64);
    int o = (idx / 64) % 64;
    int c = idx % 64;
    float v = w_def[o*576 + c*9 + k];           // w_def[o][c][k][0]
    __nv_bfloat16 hi = __float2bfloat16(v);
    __nv_bfloat16 lo = __float2bfloat16(v - __bfloat162float(hi));
    g_wbf[((size_t)(k*2+0)*64 + o)*WPAD + c] = hi;
    g_wbf[((size_t)(k*2+1)*64 + o)*WPAD + c] = lo;
}

// ---------------- kernel A: offset conv (9 odd channels) + partial stats ----------------
__global__ __launch_bounds__(256) void offset_conv_kernel(
        const float* __restrict__ x,
        const float* __restrict__ w_off,
        const float* __restrict__ b_off) {
    __shared__ float wsm[576*12];
    __shared__ float bo[KKK];
    __shared__ float red[8*18];

    int tid = threadIdx.x;
    for (int e = tid; e < 576*9; e += 256) {
        int j = e % 9;
        int ck = e / 9;
        wsm[ck*12 + j] = w_off[(2*j+1)*576 + ck];
    }
    if (tid < 9) bo[tid] = b_off[2*tid+1];
    __syncthreads();

    int g  = blockIdx.x*256 + tid;
    int w4 = g % 40;
    int h  = (g/40) % HH;
    int b  = g / (40*HH);

    float4 acc[9];
#pragma unroll
    for (int j = 0; j < 9; j++) acc[j] = make_float4(bo[j], bo[j], bo[j], bo[j]);

    const float* xb = x + (size_t)b*CIN*HWSZ + w4*4;

#pragma unroll
    for (int ky = 0; ky < 9; ky++) {
        int row = h - PADK + ky;
        if ((unsigned)row >= (unsigned)HH) continue;
        const float* xr = xb + row*WW;
#pragma unroll 4
        for (int c = 0; c < CIN; c++) {
            float4 xv = *(const float4*)(xr + c*HWSZ);
            const float* wr = &wsm[(c*9 + ky)*12];
            float4 wA = *(const float4*)wr;
            float4 wB = *(const float4*)(wr + 4);
            float  w8 = wr[8];
#define FMA4(A, S) { A.x += xv.x*(S); A.y += xv.y*(S); A.z += xv.z*(S); A.w += xv.w*(S); }
            FMA4(acc[0], wA.x); FMA4(acc[1], wA.y); FMA4(acc[2], wA.z); FMA4(acc[3], wA.w);
            FMA4(acc[4], wB.x); FMA4(acc[5], wB.y); FMA4(acc[6], wB.z); FMA4(acc[7], wB.w);
            FMA4(acc[8], w8);
#undef FMA4
        }
    }

#pragma unroll
    for (int j = 0; j < 9; j++) {
        *(float4*)&g_off9[((size_t)(b*9 + j)*HH + h)*WW + w4*4] = acc[j];
    }

    float ls[9], ls2[9];
#pragma unroll
    for (int j = 0; j < 9; j++) {
        float4 a = acc[j];
        ls[j]  = a.x + a.y + a.z + a.w;
        ls2[j] = a.x*a.x + a.y*a.y + a.z*a.z + a.w*a.w;
    }
#pragma unroll
    for (int off = 16; off > 0; off >>= 1) {
#pragma unroll
        for (int j = 0; j < 9; j++) {
            ls[j]  += __shfl_down_sync(0xffffffffu, ls[j],  off);
            ls2[j] += __shfl_down_sync(0xffffffffu, ls2[j], off);
        }
    }
    int lane = tid & 31, wid = tid >> 5;
    if (lane == 0) {
#pragma unroll
        for (int j = 0; j < 9; j++) {
            red[wid*18 + j]     = ls[j];
            red[wid*18 + 9 + j] = ls2[j];
        }
    }
    __syncthreads();
    if (tid < 18) {
        float s = 0.f;
#pragma unroll
        for (int i = 0; i < 8; i++) s += red[i*18 + tid];
        g_partials[blockIdx.x*18 + tid] = s;
    }
}

// ---------------- kernel B: finalize stats ----------------
__global__ void stats_kernel(const float* __restrict__ gamma,
                             const float* __restrict__ beta) {
    __shared__ float sm[18];
    int tid = threadIdx.x;
    if (tid < 18) {
        float s = 0.f;
        for (int i = 0; i < NBLK_A; i++) s += g_partials[i*18 + tid];
        sm[tid] = s;
    }
    __syncthreads();
    if (tid < 9) {
        float mean = sm[tid] * (1.0f/(float)NPIX);
        float var  = sm[9+tid] * (1.0f/(float)NPIX) - mean*mean;
        float rstd = rsqrtf(fmaxf(var, 0.f) + EPSV);
        float sc   = rstd * gamma[2*tid+1];
        g_scale[tid] = sc;
        g_shift[tid] = beta[2*tid+1] - mean*sc;
    }
}

// ---------------- kernel C: deformable conv via mma.sync bf16 3-split (ldmatrix) ----------------
// Block = (h, whalf, b), 256 threads (8 warps): mi = wid&3 (o rows mi*16..+15),
// ni = wid>>2 (w cols ni*40..+39, 5 n8-tiles). Full K=64 per warp (4 k16 chunks).
// Fragments via ldmatrix; gather is div-free with hoisted tables.
// Smem bytes:
//   [0] W_hi 9216 | [9216] W_lo 9216 | [18432] S_hi 11520 | [29952] S_lo 11520
//   [41472] sw01 float2[720] 5760 | [47232] a01 short2[720] 2880  -> 50112
#define SM_WHI 0
#define SM_WLO 9216
#define SM_SHI 18432
#define SM_SLO 29952
#define SM_TBL 41472
#define SMEM_BYTES 50112

extern __shared__ unsigned char smraw[];

__device__ __forceinline__ void mma_bf16(float* d, const uint32_t* a, const uint32_t* bfr) {
    asm volatile(
        "mma.sync.aligned.m16n8k16.row.col.f32.bf16.bf16.f32 "
        "{%0,%1,%2,%3}, {%4,%5,%6,%7}, {%8,%9}, {%0,%1,%2,%3};"
        : "+f"(d[0]), "+f"(d[1]), "+f"(d[2]), "+f"(d[3])
        : "r"(a[0]), "r"(a[1]), "r"(a[2]), "r"(a[3]), "r"(bfr[0]), "r"(bfr[1]));
}
__device__ __forceinline__ void ldsm_x4(uint32_t addr, uint32_t* r) {
    asm volatile("ldmatrix.sync.aligned.m8n8.x4.shared.b16 {%0,%1,%2,%3}, [%4];"
        : "=r"(r[0]), "=r"(r[1]), "=r"(r[2]), "=r"(r[3]) : "r"(addr));
}
__device__ __forceinline__ void ldsm_x2(uint32_t addr, uint32_t* r) {
    asm volatile("ldmatrix.sync.aligned.m8n8.x2.shared.b16 {%0,%1}, [%2];"
        : "=r"(r[0]), "=r"(r[1]) : "r"(addr));
}

__global__ __launch_bounds__(256, 4) void deform_mma_kernel(
        const float* __restrict__ x,
        const float* __restrict__ b_def,
        float* __restrict__ out) {
    float2* sw01 = (float2*)(smraw + SM_TBL);
    short2* a01  = (short2*)(smraw + SM_TBL + 5760);

    int tid = threadIdx.x;
    int lane = tid & 31;
    int wid  = tid >> 5;
    int h  = blockIdx.x;
    int w0 = blockIdx.y * WT;
    int b  = blockIdx.z;

    // ---- phase 0: offsets ----
    if (tid < WT) {
        int w = w0 + tid;
        float y[9], dx[9];
#pragma unroll
        for (int k = 0; k < 9; k++) {
            float v = g_off9[((size_t)(b*9 + k)*HH + h)*WW + w];
            y[k] = tanhf(v*g_scale[k] + g_shift[k]);
        }
        dx[4] = y[4];
        float a = y[4];
#pragma unroll
        for (int k = 3; k >= 0; k--) { a += y[k]; dx[k] = a; }
        a = y[4];
#pragma unroll
        for (int k = 5; k < 9; k++) { a += y[k]; dx[k] = a; }
#pragma unroll
        for (int k = 0; k < 9; k++) {
            float px = (float)w + dx[k];
            float fl = floorf(px);
            float fx = px - fl;
            int   x0 = (int)fl;
            float w0v = (x0 >= 0 && x0 < WW)      ? (1.f - fx) : 0.f;
            float w1v = (x0 >= -1 && x0 < WW - 1) ? fx         : 0.f;
            sw01[k*WT + tid] = make_float2(w0v, w1v);
            a01[k*WT + tid]  = make_short2((short)min(max(x0,     0), WW - 1),
                                           (short)min(max(x0 + 1, 0), WW - 1));
        }
    }

    const int mi = wid & 3;          // o tile: rows mi*16..+15
    const int ni = wid >> 2;         // w half: cols ni*40..+39
    const int grp = lane >> 2;       // 0..7
    const int tig = lane & 3;        // 0..3
    const int mat = lane >> 3;       // ldmatrix sub-matrix id
    const int rowin = lane & 7;

    uint32_t sbase = (uint32_t)__cvta_generic_to_shared(smraw);
    // ldmatrix per-lane offsets (verified by R14 pass)
    const uint32_t aoff  = (uint32_t)((mat & 1)*8*144 + rowin*144 + (mat >> 1)*16);
    const uint32_t boff4 = (uint32_t)((mat >> 1)*8*144 + rowin*144 + (mat & 1)*16);
    const uint32_t boff2 = (uint32_t)(rowin*144 + (mat & 1)*16);

    float acc[5][4];
#pragma unroll
    for (int nt = 0; nt < 5; nt++)
#pragma unroll
        for (int j = 0; j < 4; j++) acc[nt][j] = 0.f;

    const float* xbatch = x + (size_t)b*CIN*HWSZ;

    // div-free gather assignment (computed once)
    const int gw  = tid % WT;        // fixed w column
    const int cp0 = tid / WT;        // 0..3; threads with cp0==3 idle in gather

    int r0 = max(h - PADK, 0);
    int r1 = min(h + PADK, HH - 1);
    int nk = r1 - r0 + 1;
    int k0 = r0 - h + PADK;

    for (int i = 0; i < nk; i++) {
        int k = k0 + i;
        __syncthreads();   // phase-0 done / smem free for reuse

        // stage split W tiles (18432 B straight copy)
        {
            const float4* wsrc = (const float4*)(g_wbf + (size_t)k*2*64*WPAD);
            float4* wdst = (float4*)(smraw + SM_WHI);
            for (int t = tid; t < 1152; t += 256) wdst[t] = wsrc[t];
        }
        // gather + interpolate + bf16-split S[w][c] (hi/lo); fixed w, cp strides by 3
        if (cp0 < 3) {
            const float* xrow = xbatch + (size_t)(r0 + i)*WW;
            float2 iw = sw01[k*WT + gw];
            short2 aa = a01[k*WT + gw];
            const float* p0 = xrow + aa.x + (size_t)cp0*2*HWSZ;
            const float* p1 = xrow + aa.y + (size_t)cp0*2*HWSZ;
            uint32_t off = (uint32_t)gw*144 + (uint32_t)cp0*4;
            for (int cp = cp0; cp < 32; cp += 3) {
                float v0 = iw.x*__ldg(p0)        + iw.y*__ldg(p1);
                float v1 = iw.x*__ldg(p0 + HWSZ) + iw.y*__ldg(p1 + HWSZ);
                __nv_bfloat16 h0 = __float2bfloat16(v0);
                __nv_bfloat16 h1 = __float2bfloat16(v1);
                float l0 = v0 - __bfloat162float(h0);
                float l1 = v1 - __bfloat162float(h1);
                uint32_t hpair = ((uint32_t)__bfloat16_as_ushort(h1) << 16)
                               |  (uint32_t)__bfloat16_as_ushort(h0);
                uint32_t lpair;
                asm("cvt.rn.bf16x2.f32 %0, %1, %2;" : "=r"(lpair) : "f"(l1), "f"(l0));
                *(uint32_t*)(smraw + SM_SHI + off) = hpair;
                *(uint32_t*)(smraw + SM_SLO + off) = lpair;
                p0 += 6*HWSZ; p1 += 6*HWSZ; off += 12;
            }
        }
        __syncthreads();

        // GEMM: 4 k16 chunks, fragments via ldmatrix
#pragma unroll
        for (int kc = 0; kc < 4; kc++) {
            uint32_t kb = (uint32_t)kc*32;
            uint32_t ah[4], al[4];
            ldsm_x4(sbase + SM_WHI + (uint32_t)(mi*16)*144 + aoff + kb, ah);
            ldsm_x4(sbase + SM_WLO + (uint32_t)(mi*16)*144 + aoff + kb, al);
#pragma unroll
            for (int ntp = 0; ntp < 2; ntp++) {
                uint32_t bh[4], bl[4];
                uint32_t bb = (uint32_t)(ni*40 + ntp*16)*144 + boff4 + kb;
                ldsm_x4(sbase + SM_SHI + bb, bh);
                ldsm_x4(sbase + SM_SLO + bb, bl);
                int nt = 2*ntp;
                mma_bf16(acc[nt],   ah, bh);    mma_bf16(acc[nt],   ah, bl);
                mma_bf16(acc[nt],   al, bh);
                mma_bf16(acc[nt+1], ah, bh+2);  mma_bf16(acc[nt+1], ah, bl+2);
                mma_bf16(acc[nt+1], al, bh+2);
            }
            {   // tile nt=4
                uint32_t bh[2], bl[2];
                uint32_t bb = (uint32_t)(ni*40 + 32)*144 + boff2 + kb;
                ldsm_x2(sbase + SM_SHI + bb, bh);
                ldsm_x2(sbase + SM_SLO + bb, bl);
                mma_bf16(acc[4], ah, bh);  mma_bf16(acc[4], ah, bl);
                mma_bf16(acc[4], al, bh);
            }
        }
    }

    // ---- epilogue: add bias, store float2 pairs ----
    int o0 = mi*16 + grp;
    int o1 = o0 + 8;
    float bv0 = __ldg(&b_def[o0]);
    float bv1 = __ldg(&b_def[o1]);
#pragma unroll
    for (int nt = 0; nt < 5; nt++) {
        int wcol = w0 + ni*40 + nt*8 + tig*2;
        float2 q0 = make_float2(acc[nt][0] + bv0, acc[nt][1] + bv0);
        float2 q1 = make_float2(acc[nt][2] + bv1, acc[nt][3] + bv1);
        *(float2*)&out[(((size_t)b*COUT + o0)*HH + h)*WW + wcol] = q0;
        *(float2*)&out[(((size_t)b*COUT + o1)*HH + h)*WW + wcol] = q1;
    }
}

// ---------------- launch ----------------
extern "C" void kernel_launch(void* const* d_in, const int* in_sizes, int n_in,
                              void* d_out, int out_size) {
    const float* x     = (const float*)d_in[0];
    const float* w_off = (const float*)d_in[1];
    const float* b_off = (const float*)d_in[2];
    const float* gamma = (const float*)d_in[3];
    const float* beta  = (const float*)d_in[4];
    const float* w_def = (const float*)d_in[5];
    const float* b_def = (const float*)d_in[6];
    float* out = (float*)d_out;

    static bool attr_set = false;
    if (!attr_set) {
        cudaFuncSetAttribute(deform_mma_kernel,
                             cudaFuncAttributeMaxDynamicSharedMemorySize, SMEM_BYTES);
        attr_set = true;
    }

    wprep_kernel<<<(KKK*64*64 + 255)/256, 256>>>(w_def);
    offset_conv_kernel<<<NBLK_A, 256>>>(x, w_off, b_off);
    stats_kernel<<<1, 32>>>(gamma, beta);
    deform_mma_kernel<<<dim3(HH, WW/WT, BB), 256, SMEM_BYTES>>>(x, b_def, out);
}

// round 16
// speedup vs baseline: 2.1686x; 1.0805x over previous
#include <cuda_runtime.h>
#include <cuda_bf16.h>
#include <math.h>
#include <stdint.h>

#define HH 160
#define WW 160
#define BB 4
#define CIN 64
#define COUT 64
#define KKK 9
#define PADK 4
#define HWSZ (HH*WW)
#define NPIX (BB*HH*WW)      /* 102400 */
#define EPSV 1e-5f
#define NBLK_A 100
#define WT 80                /* w-tile per deform block */

// ---------------- device scratch ----------------
__device__ __align__(16) float g_off9[BB*KKK*HH*WW];
__device__ float g_partials[NBLK_A*18];
__device__ float g_scale[KKK];
__device__ float g_shift[KKK];
// weight fragments in mma order: [k][hi|lo][mi(4)][kc(4)][lane(32)] = uint4 (a0..a3)
__device__ __align__(16) uint4 g_wfrag[KKK*2*4*4*32];

// ---------------- kernel P: prep weight fragments ----------------
// idx -> (k, sp, mi, kc, lane); a0=[g][2t,2t+1], a1=[g+8][..], a2=[g][2t+8,..], a3=[g+8][2t+8,..]
__global__ void wprep_kernel(const float* __restrict__ w_def) {
    int idx = blockIdx.x*256 + threadIdx.x;
    if (idx >= KKK*2*4*4*32) return;
    int lane = idx & 31;
    int kc   = (idx >> 5) & 3;
    int mi   = (idx >> 7) & 3;
    int sp   = (idx >> 9) & 1;
    int k    = idx >> 10;
    int g = lane >> 2;
    int t = lane & 3;

    uint32_t r[4];
#pragma unroll
    for (int j = 0; j < 4; j++) {
        int o = mi*16 + g + ((j & 1) ? 8 : 0);
        int c = kc*16 + t*2 + ((j & 2) ? 8 : 0);
        float v0 = w_def[o*576 + c*9 + k];         // w_def[o][c][k][0]
        float v1 = w_def[o*576 + (c+1)*9 + k];
        if (sp == 0) {
            __nv_bfloat16 h0 = __float2bfloat16(v0);
            __nv_bfloat16 h1 = __float2bfloat16(v1);
            r[j] = ((uint32_t)__bfloat16_as_ushort(h1) << 16) | (uint32_t)__bfloat16_as_ushort(h0);
        } else {
            __nv_bfloat16 h0 = __float2bfloat16(v0);
            __nv_bfloat16 h1 = __float2bfloat16(v1);
            __nv_bfloat16 l0 = __float2bfloat16(v0 - __bfloat162float(h0));
            __nv_bfloat16 l1 = __float2bfloat16(v1 - __bfloat162float(h1));
            r[j] = ((uint32_t)__bfloat16_as_ushort(l1) << 16) | (uint32_t)__bfloat16_as_ushort(l0);
        }
    }
    g_wfrag[idx] = make_uint4(r[0], r[1], r[2], r[3]);
}

// ---------------- kernel A: offset conv (9 odd channels) + partial stats ----------------
__global__ __launch_bounds__(256) void offset_conv_kernel(
        const float* __restrict__ x,
        const float* __restrict__ w_off,
        const float* __restrict__ b_off) {
    __shared__ float wsm[576*12];
    __shared__ float bo[KKK];
    __shared__ float red[8*18];

    int tid = threadIdx.x;
    for (int e = tid; e < 576*9; e += 256) {
        int j = e % 9;
        int ck = e / 9;
        wsm[ck*12 + j] = w_off[(2*j+1)*576 + ck];
    }
    if (tid < 9) bo[tid] = b_off[2*tid+1];
    __syncthreads();

    int g  = blockIdx.x*256 + tid;
    int w4 = g % 40;
    int h  = (g/40) % HH;
    int b  = g / (40*HH);

    float4 acc[9];
#pragma unroll
    for (int j = 0; j < 9; j++) acc[j] = make_float4(bo[j], bo[j], bo[j], bo[j]);

    const float* xb = x + (size_t)b*CIN*HWSZ + w4*4;

#pragma unroll
    for (int ky = 0; ky < 9; ky++) {
        int row = h - PADK + ky;
        if ((unsigned)row >= (unsigned)HH) continue;
        const float* xr = xb + row*WW;
#pragma unroll 4
        for (int c = 0; c < CIN; c++) {
            float4 xv = *(const float4*)(xr + c*HWSZ);
            const float* wr = &wsm[(c*9 + ky)*12];
            float4 wA = *(const float4*)wr;
            float4 wB = *(const float4*)(wr + 4);
            float  w8 = wr[8];
#define FMA4(A, S) { A.x += xv.x*(S); A.y += xv.y*(S); A.z += xv.z*(S); A.w += xv.w*(S); }
            FMA4(acc[0], wA.x); FMA4(acc[1], wA.y); FMA4(acc[2], wA.z); FMA4(acc[3], wA.w);
            FMA4(acc[4], wB.x); FMA4(acc[5], wB.y); FMA4(acc[6], wB.z); FMA4(acc[7], wB.w);
            FMA4(acc[8], w8);
#undef FMA4
        }
    }

#pragma unroll
    for (int j = 0; j < 9; j++) {
        *(float4*)&g_off9[((size_t)(b*9 + j)*HH + h)*WW + w4*4] = acc[j];
    }

    float ls[9], ls2[9];
#pragma unroll
    for (int j = 0; j < 9; j++) {
        float4 a = acc[j];
        ls[j]  = a.x + a.y + a.z + a.w;
        ls2[j] = a.x*a.x + a.y*a.y + a.z*a.z + a.w*a.w;
    }
#pragma unroll
    for (int off = 16; off > 0; off >>= 1) {
#pragma unroll
        for (int j = 0; j < 9; j++) {
            ls[j]  += __shfl_down_sync(0xffffffffu, ls[j],  off);
            ls2[j] += __shfl_down_sync(0xffffffffu, ls2[j], off);
        }
    }
    int lane = tid & 31, wid = tid >> 5;
    if (lane == 0) {
#pragma unroll
        for (int j = 0; j < 9; j++) {
            red[wid*18 + j]     = ls[j];
            red[wid*18 + 9 + j] = ls2[j];
        }
    }
    __syncthreads();
    if (tid < 18) {
        float s = 0.f;
#pragma unroll
        for (int i = 0; i < 8; i++) s += red[i*18 + tid];
        g_partials[blockIdx.x*18 + tid] = s;
    }
}

// ---------------- kernel B: finalize stats ----------------
__global__ void stats_kernel(const float* __restrict__ gamma,
                             const float* __restrict__ beta) {
    __shared__ float sm[18];
    int tid = threadIdx.x;
    if (tid < 18) {
        float s = 0.f;
        for (int i = 0; i < NBLK_A; i++) s += g_partials[i*18 + tid];
        sm[tid] = s;
    }
    __syncthreads();
    if (tid < 9) {
        float mean = sm[tid] * (1.0f/(float)NPIX);
        float var  = sm[9+tid] * (1.0f/(float)NPIX) - mean*mean;
        float rstd = rsqrtf(fmaxf(var, 0.f) + EPSV);
        float sc   = rstd * gamma[2*tid+1];
        g_scale[tid] = sc;
        g_shift[tid] = beta[2*tid+1] - mean*sc;
    }
}

// ---------------- kernel C: deform conv, mma bf16 3-split, W frags from gmem, S pipelined ----------------
// Block = (h, whalf, b), 256 threads (8 warps): mi = wid&3, ni = wid>>2.
// S double-buffered (gather k+1 overlaps MMA k); 1 barrier per k.
// Smem bytes:
//   buf0: S_hi 11520 | S_lo 11520   buf1 at +23040
//   [46080] sw01 float2[720] 5760 | [51840] a01 short2[720] 2880  -> 54720
#define SM_SBUF(bf) ((bf)*23040)
#define SM_TBL 46080
#define SMEM_BYTES 54720

extern __shared__ unsigned char smraw[];

__device__ __forceinline__ void mma_bf16(float* d, const uint32_t* a, const uint32_t* bfr) {
    asm volatile(
        "mma.sync.aligned.m16n8k16.row.col.f32.bf16.bf16.f32 "
        "{%0,%1,%2,%3}, {%4,%5,%6,%7}, {%8,%9}, {%0,%1,%2,%3};"
        : "+f"(d[0]), "+f"(d[1]), "+f"(d[2]), "+f"(d[3])
        : "r"(a[0]), "r"(a[1]), "r"(a[2]), "r"(a[3]), "r"(bfr[0]), "r"(bfr[1]));
}
__device__ __forceinline__ void ldsm_x4(uint32_t addr, uint32_t* r) {
    asm volatile("ldmatrix.sync.aligned.m8n8.x4.shared.b16 {%0,%1,%2,%3}, [%4];"
        : "=r"(r[0]), "=r"(r[1]), "=r"(r[2]), "=r"(r[3]) : "r"(addr));
}
__device__ __forceinline__ void ldsm_x2(uint32_t addr, uint32_t* r) {
    asm volatile("ldmatrix.sync.aligned.m8n8.x2.shared.b16 {%0,%1}, [%2];"
        : "=r"(r[0]), "=r"(r[1]) : "r"(addr));
}

__global__ __launch_bounds__(256, 4) void deform_mma_kernel(
        const float* __restrict__ x,
        const float* __restrict__ b_def,
        float* __restrict__ out) {
    float2* sw01 = (float2*)(smraw + SM_TBL);
    short2* a01  = (short2*)(smraw + SM_TBL + 5760);

    int tid = threadIdx.x;
    int lane = tid & 31;
    int wid  = tid >> 5;
    int h  = blockIdx.x;
    int w0 = blockIdx.y * WT;
    int b  = blockIdx.z;

    // ---- phase 0: offsets ----
    if (tid < WT) {
        int w = w0 + tid;
        float y[9], dx[9];
#pragma unroll
        for (int k = 0; k < 9; k++) {
            float v = g_off9[((size_t)(b*9 + k)*HH + h)*WW + w];
            y[k] = tanhf(v*g_scale[k] + g_shift[k]);
        }
        dx[4] = y[4];
        float a = y[4];
#pragma unroll
        for (int k = 3; k >= 0; k--) { a += y[k]; dx[k] = a; }
        a = y[4];
#pragma unroll
        for (int k = 5; k < 9; k++) { a += y[k]; dx[k] = a; }
#pragma unroll
        for (int k = 0; k < 9; k++) {
            float px = (float)w + dx[k];
            float fl = floorf(px);
            float fx = px - fl;
            int   x0 = (int)fl;
            float w0v = (x0 >= 0 && x0 < WW)      ? (1.f - fx) : 0.f;
            float w1v = (x0 >= -1 && x0 < WW - 1) ? fx         : 0.f;
            sw01[k*WT + tid] = make_float2(w0v, w1v);
            a01[k*WT + tid]  = make_short2((short)min(max(x0,     0), WW - 1),
                                           (short)min(max(x0 + 1, 0), WW - 1));
        }
    }

    const int mi = wid & 3;          // o tile: rows mi*16..+15
    const int ni = wid >> 2;         // w half: cols ni*40..+39
    const int grp = lane >> 2;       // 0..7
    const int tig = lane & 3;        // 0..3
    const int mat = lane >> 3;       // ldmatrix sub-matrix id
    const int rowin = lane & 7;

    uint32_t sbase = (uint32_t)__cvta_generic_to_shared(smraw);
    const uint32_t boff4 = (uint32_t)((mat >> 1)*8*144 + rowin*144 + (mat & 1)*16);
    const uint32_t boff2 = (uint32_t)(rowin*144 + (mat & 1)*16);

    float acc[5][4];
#pragma unroll
    for (int nt = 0; nt < 5; nt++)
#pragma unroll
        for (int j = 0; j < 4; j++) acc[nt][j] = 0.f;

    const float* xbatch = x + (size_t)b*CIN*HWSZ;

    const int gw  = tid % WT;        // fixed gather w column
    const int cp0 = tid / WT;        // 0..3; cp0==3 idle in gather

    int r0 = max(h - PADK, 0);
    int r1 = min(h + PADK, HH - 1);
    int nk = r1 - r0 + 1;
    int k0 = r0 - h + PADK;

    __syncthreads();   // tables ready

    // gather helper expressed inline: buf target base, row index r0+i, k index
#define GATHER(KIDX, ROW, BUF) do {                                              \
        if (cp0 < 3) {                                                           \
            const float* xrow = xbatch + (size_t)(ROW)*WW;                       \
            float2 iw = sw01[(KIDX)*WT + gw];                                    \
            short2 aa = a01[(KIDX)*WT + gw];                                     \
            const float* p0 = xrow + aa.x + (size_t)cp0*2*HWSZ;                  \
            const float* p1 = xrow + aa.y + (size_t)cp0*2*HWSZ;                  \
            uint32_t off = SM_SBUF(BUF) + (uint32_t)gw*144 + (uint32_t)cp0*4;    \
            for (int cp = cp0; cp < 32; cp += 3) {                               \
                float v0 = iw.x*__ldg(p0)        + iw.y*__ldg(p1);               \
                float v1 = iw.x*__ldg(p0 + HWSZ) + iw.y*__ldg(p1 + HWSZ);        \
                __nv_bfloat16 h0 = __float2bfloat16(v0);                         \
                __nv_bfloat16 h1 = __float2bfloat16(v1);                         \
                float l0 = v0 - __bfloat162float(h0);                            \
                float l1 = v1 - __bfloat162float(h1);                            \
                uint32_t hpair = ((uint32_t)__bfloat16_as_ushort(h1) << 16)      \
                               |  (uint32_t)__bfloat16_as_ushort(h0);            \
                uint32_t lpair;                                                  \
                asm("cvt.rn.bf16x2.f32 %0, %1, %2;" : "=r"(lpair) : "f"(l1), "f"(l0)); \
                *(uint32_t*)(smraw + off)         = hpair;                       \
                *(uint32_t*)(smraw + off + 11520) = lpair;                       \
                p0 += 6*HWSZ; p1 += 6*HWSZ; off += 12;                           \
            }                                                                    \
        }                                                                        \
    } while (0)

    // prologue
    GATHER(k0, r0, 0);
    __syncthreads();

    int buf = 0;
    for (int i = 0; i < nk; i++) {
        int k = k0 + i;

        // gather k+1 into other buffer (overlaps MMA below)
        if (i + 1 < nk) GATHER(k + 1, r0 + i + 1, buf ^ 1);

        // MMA for k from buf; A fragments direct from gmem (coalesced LDG.128)
        const uint4* wfh = &g_wfrag[(((size_t)k*2 + 0)*4 + mi)*4*32 + lane];
        const uint4* wfl = &g_wfrag[(((size_t)k*2 + 1)*4 + mi)*4*32 + lane];
        uint32_t sb = sbase + SM_SBUF(buf);
#pragma unroll
        for (int kc = 0; kc < 4; kc++) {
            uint4 ahv = __ldg(wfh + kc*32);
            uint4 alv = __ldg(wfl + kc*32);
            uint32_t ah[4] = {ahv.x, ahv.y, ahv.z, ahv.w};
            uint32_t al[4] = {alv.x, alv.y, alv.z, alv.w};
            uint32_t kb = (uint32_t)kc*32;
#pragma unroll
            for (int ntp = 0; ntp < 2; ntp++) {
                uint32_t bh[4], bl[4];
                uint32_t bb = (uint32_t)(ni*40 + ntp*16)*144 + boff4 + kb;
                ldsm_x4(sb + bb, bh);
                ldsm_x4(sb + 11520 + bb, bl);
                int nt = 2*ntp;
                mma_bf16(acc[nt],   ah, bh);    mma_bf16(acc[nt],   ah, bl);
                mma_bf16(acc[nt],   al, bh);
                mma_bf16(acc[nt+1], ah, bh+2);  mma_bf16(acc[nt+1], ah, bl+2);
                mma_bf16(acc[nt+1], al, bh+2);
            }
            {   // tile nt=4
                uint32_t bh[2], bl[2];
                uint32_t bb = (uint32_t)(ni*40 + 32)*144 + boff2 + kb;
                ldsm_x2(sb + bb, bh);
                ldsm_x2(sb + 11520 + bb, bl);
                mma_bf16(acc[4], ah, bh);  mma_bf16(acc[4], ah, bl);
                mma_bf16(acc[4], al, bh);
            }
        }
        __syncthreads();   // buf^1 published; buf free for overwrite
        buf ^= 1;
    }
#undef GATHER

    // ---- epilogue: add bias, store float2 pairs ----
    int o0 = mi*16 + grp;
    int o1 = o0 + 8;
    float bv0 = __ldg(&b_def[o0]);
    float bv1 = __ldg(&b_def[o1]);
#pragma unroll
    for (int nt = 0; nt < 5; nt++) {
        int wcol = w0 + ni*40 + nt*8 + tig*2;
        float2 q0 = make_float2(acc[nt][0] + bv0, acc[nt][1] + bv0);
        float2 q1 = make_float2(acc[nt][2] + bv1, acc[nt][3] + bv1);
        *(float2*)&out[(((size_t)b*COUT + o0)*HH + h)*WW + wcol] = q0;
        *(float2*)&out[(((size_t)b*COUT + o1)*HH + h)*WW + wcol] = q1;
    }
}

// ---------------- launch ----------------
extern "C" void kernel_launch(void* const* d_in, const int* in_sizes, int n_in,
                              void* d_out, int out_size) {
    const float* x     = (const float*)d_in[0];
    const float* w_off = (const float*)d_in[1];
    const float* b_off = (const float*)d_in[2];
    const float* gamma = (const float*)d_in[3];
    const float* beta  = (const float*)d_in[4];
    const float* w_def = (const float*)d_in[5];
    const float* b_def = (const float*)d_in[6];
    float* out = (float*)d_out;

    static bool attr_set = false;
    if (!attr_set) {
        cudaFuncSetAttribute(deform_mma_kernel,
                             cudaFuncAttributeMaxDynamicSharedMemorySize, SMEM_BYTES);
        attr_set = true;
    }

    wprep_kernel<<<(KKK*2*4*4*32 + 255)/256, 256>>>(w_def);
    offset_conv_kernel<<<NBLK_A, 256>>>(x, w_off, b_off);
    stats_kernel<<<1, 32>>>(gamma, beta);
    deform_mma_kernel<<<dim3(HH, WW/WT, BB), 256, SMEM_BYTES>>>(x, b_def, out);
}